// round 6
// baseline (speedup 1.0000x reference)
#include <cuda_runtime.h>
#include <cuda_bf16.h>
#include <cstdint>
#include <math.h>

#define NP    2048
#define DFEAT 256
#define BTM   128
#define BTN   256
#define NBX   (NP / BTN)       // 8
#define NBY   (NP / BTM)       // 16
#define NCTAS (NBX * NBY)      // 128

// smem rows padded: 256 bf16 + 8 pad = 528 B
#define ROWB   528
#define A_B    (BTM * ROWB)            // 67584
#define B_B    (BTN * ROWB)            // 135168
#define SM_A   0
#define SM_B   A_B
#define SM_RS  (A_B + B_B)             // rsum[128] floats
#define SM_CS  (A_B + B_B + 512)       // csum[256] floats
#define SM_RED (A_B + B_B + 512 + 1024)// red[512] floats
#define SMEM_TOTAL (SM_RED + 2048)     // 206336 B

// -------- device scratch --------
__device__ float g_RowP[NBX][NP];
__device__ float g_ColP[NBY][NP];
__device__ float g_Dpos[NP];
__device__ unsigned int g_done = 0;

static __device__ __forceinline__ uint32_t smem_u32(const void* p) {
    return (uint32_t)__cvta_generic_to_shared((void*)p);
}

static __device__ __forceinline__ void ldsm_x4(uint32_t* r, uint32_t addr) {
    asm volatile("ldmatrix.sync.aligned.m8n8.x4.shared.b16 {%0,%1,%2,%3}, [%4];"
                 : "=r"(r[0]), "=r"(r[1]), "=r"(r[2]), "=r"(r[3]) : "r"(addr));
}

static __device__ __forceinline__ void mma16816(float* c, const uint32_t* a,
                                                const uint32_t* b) {
    asm volatile(
        "mma.sync.aligned.m16n8k16.row.col.f32.bf16.bf16.f32 "
        "{%0,%1,%2,%3}, {%4,%5,%6,%7}, {%8,%9}, {%0,%1,%2,%3};"
        : "+f"(c[0]), "+f"(c[1]), "+f"(c[2]), "+f"(c[3])
        : "r"(a[0]), "r"(a[1]), "r"(a[2]), "r"(a[3]), "r"(b[0]), "r"(b[1]));
}

// 8 fp32 (two float4) -> 8 bf16 (one uint4), round-to-nearest
static __device__ __forceinline__ void cvt_store(void* dst, float4 v0, float4 v1) {
    __nv_bfloat162 p0 = __float22bfloat162_rn(make_float2(v0.x, v0.y));
    __nv_bfloat162 p1 = __float22bfloat162_rn(make_float2(v0.z, v0.w));
    __nv_bfloat162 p2 = __float22bfloat162_rn(make_float2(v1.x, v1.y));
    __nv_bfloat162 p3 = __float22bfloat162_rn(make_float2(v1.z, v1.w));
    uint4 u;
    u.x = *(uint32_t*)&p0; u.y = *(uint32_t*)&p1;
    u.z = *(uint32_t*)&p2; u.w = *(uint32_t*)&p3;
    *(uint4*)dst = u;
}

// ---------------------------------------------------------------------------
// Single fused kernel: convert + GEMM(E = Xeven . Xodd^T) + exp epilogue +
// last-CTA finalize. 512 threads = 16 warps (4M x 4N), tile 128x256, 1 wave.
// K is processed in 4 chunks of 64 with register-staged prefetch.
// ---------------------------------------------------------------------------
__global__ __launch_bounds__(512, 1)
void sml_fused(const float* __restrict__ X, float* __restrict__ out) {
    extern __shared__ char smem[];
    const uint32_t sbase = smem_u32(smem);
    float* rsum = (float*)(smem + SM_RS);
    float* csum = (float*)(smem + SM_CS);

    const int tid = threadIdx.x;
    const int wid = tid >> 5;
    const int l   = tid & 31;
    const int wm  = wid & 3;
    const int wn  = wid >> 2;
    const int bx = blockIdx.x, by = blockIdx.y;
    const int r0 = by * BTM, c0 = bx * BTN;

    if (tid < 128) rsum[tid] = 0.0f;
    if (tid < 256) csum[tid] = 0.0f;

    // Per-thread loader slots: A has 1024 uint4-stores/chunk, B has 2048.
    // A: i in 0..1, idx = tid + 512*i -> row = idx>>3 (0..127), u = idx&7
    // B: i in 0..3, idx = tid + 512*i -> row = idx>>3 (0..255), u = idx&7
    // global fp32 source (chunk c): Xrow*256 + c*64 + u*8
    // smem dst: row*ROWB + (c*8+u)*16
    // ---- chunk 0: direct load+convert+store ----
#pragma unroll
    for (int i = 0; i < 2; i++) {
        const int idx = tid + 512 * i;
        const int row = idx >> 3, u = idx & 7;
        const float4* s = (const float4*)(X + (size_t)(2 * (r0 + row)) * DFEAT) + u * 2;
        cvt_store(smem + SM_A + row * ROWB + u * 16, s[0], s[1]);
    }
#pragma unroll
    for (int i = 0; i < 4; i++) {
        const int idx = tid + 512 * i;
        const int row = idx >> 3, u = idx & 7;
        const float4* s = (const float4*)(X + (size_t)(2 * (c0 + row) + 1) * DFEAT) + u * 2;
        cvt_store(smem + SM_B + row * ROWB + u * 16, s[0], s[1]);
    }
    __syncthreads();

    // ---- ldmatrix lane addressing (validated) ----
    const int a_row = (l & 7) + 8 * ((l >> 3) & 1);
    const int a_kb  = 16 * ((l >> 4) & 1);
    const int b_row = (l & 7) + 8 * ((l >> 4) & 1);
    const int b_kb  = 16 * ((l >> 3) & 1);
    const uint32_t aAddr0 = sbase + SM_A + (uint32_t)(wm * 32 + a_row) * ROWB + a_kb;
    const uint32_t bAddr0 = sbase + SM_B + (uint32_t)(wn * 64 + b_row) * ROWB + b_kb;

    float acc[2][8][4];
#pragma unroll
    for (int mt = 0; mt < 2; mt++)
#pragma unroll
        for (int nt = 0; nt < 8; nt++)
#pragma unroll
            for (int r = 0; r < 4; r++) acc[mt][nt][r] = 0.0f;

    // ---- mainloop: 4 chunks of K=64, prefetch chunk c+1 in registers ----
    float4 st[12];
#pragma unroll
    for (int c = 0; c < 4; c++) {
        if (c < 3) {
#pragma unroll
            for (int i = 0; i < 2; i++) {
                const int idx = tid + 512 * i;
                const int row = idx >> 3, u = idx & 7;
                const float4* s = (const float4*)(X + (size_t)(2 * (r0 + row)) * DFEAT)
                                  + (c + 1) * 16 + u * 2;
                st[i * 2] = s[0];  st[i * 2 + 1] = s[1];
            }
#pragma unroll
            for (int i = 0; i < 4; i++) {
                const int idx = tid + 512 * i;
                const int row = idx >> 3, u = idx & 7;
                const float4* s = (const float4*)(X + (size_t)(2 * (c0 + row) + 1) * DFEAT)
                                  + (c + 1) * 16 + u * 2;
                st[4 + i * 2] = s[0];  st[4 + i * 2 + 1] = s[1];
            }
        }

        // compute 4 K-steps of chunk c
#pragma unroll
        for (int kk = 0; kk < 4; kk++) {
            const uint32_t koff = (uint32_t)(c * 4 + kk) * 32;
            uint32_t a[2][4];
            ldsm_x4(a[0], aAddr0 + koff);
            ldsm_x4(a[1], aAddr0 + 16 * ROWB + koff);
            uint32_t b[8][2];
#pragma unroll
            for (int q = 0; q < 4; q++) {
                uint32_t t[4];
                ldsm_x4(t, bAddr0 + (uint32_t)(q * 16) * ROWB + koff);
                b[2 * q][0] = t[0];      b[2 * q][1] = t[1];
                b[2 * q + 1][0] = t[2];  b[2 * q + 1][1] = t[3];
            }
#pragma unroll
            for (int mt = 0; mt < 2; mt++)
#pragma unroll
                for (int nt = 0; nt < 8; nt++)
                    mma16816(acc[mt][nt], a[mt], b[nt]);
        }

        if (c < 3) {
#pragma unroll
            for (int i = 0; i < 2; i++) {
                const int idx = tid + 512 * i;
                const int row = idx >> 3, u = idx & 7;
                cvt_store(smem + SM_A + row * ROWB + ((c + 1) * 8 + u) * 16,
                          st[i * 2], st[i * 2 + 1]);
            }
#pragma unroll
            for (int i = 0; i < 4; i++) {
                const int idx = tid + 512 * i;
                const int row = idx >> 3, u = idx & 7;
                cvt_store(smem + SM_B + row * ROWB + ((c + 1) * 8 + u) * 16,
                          st[4 + i * 2], st[4 + i * 2 + 1]);
            }
            __syncthreads();
        }
    }

    // ---- epilogue: exp, masked row/col partials, Dpos ----
    float rowp[2][2];
    float colp[8][2];
#pragma unroll
    for (int mt = 0; mt < 2; mt++)
#pragma unroll
        for (int h = 0; h < 2; h++) rowp[mt][h] = 0.0f;
#pragma unroll
    for (int nt = 0; nt < 8; nt++)
#pragma unroll
        for (int j = 0; j < 2; j++) colp[nt][j] = 0.0f;

#pragma unroll
    for (int mt = 0; mt < 2; mt++) {
#pragma unroll
        for (int h = 0; h < 2; h++) {
            const int gr = r0 + wm * 32 + mt * 16 + h * 8 + (l >> 2);
            const int rexcl = 2 * gr + 1;
#pragma unroll
            for (int nt = 0; nt < 8; nt++) {
#pragma unroll
                for (int j = 0; j < 2; j++) {
                    const int gc = c0 + wn * 64 + nt * 8 + 2 * (l & 3) + j;
                    const float e = acc[mt][nt][2 * h + j] * (1.0f / 128.0f);
                    const float x = __expf(1.0f + e);
                    if (gc != rexcl)  rowp[mt][h] += x;
                    if (gr != 2 * gc) colp[nt][j] += x;
                    if (gr == gc)     g_Dpos[gr] = e;
                }
            }
        }
    }

#pragma unroll
    for (int mt = 0; mt < 2; mt++) {
#pragma unroll
        for (int h = 0; h < 2; h++) {
            float v = rowp[mt][h];
            v += __shfl_xor_sync(0xFFFFFFFFu, v, 1);
            v += __shfl_xor_sync(0xFFFFFFFFu, v, 2);
            if ((l & 3) == 0)
                atomicAdd(&rsum[wm * 32 + mt * 16 + h * 8 + (l >> 2)], v);
        }
    }
#pragma unroll
    for (int nt = 0; nt < 8; nt++) {
#pragma unroll
        for (int j = 0; j < 2; j++) {
            float v = colp[nt][j];
            v += __shfl_xor_sync(0xFFFFFFFFu, v, 4);
            v += __shfl_xor_sync(0xFFFFFFFFu, v, 8);
            v += __shfl_xor_sync(0xFFFFFFFFu, v, 16);
            if ((l >> 2) == 0)
                atomicAdd(&csum[wn * 64 + nt * 8 + 2 * (l & 3) + j], v);
        }
    }
    __syncthreads();

    if (tid < 128) {
        g_RowP[bx][r0 + tid] = rsum[tid];
    } else if (tid < 384) {
        g_ColP[by][c0 + tid - 128] = csum[tid - 128];
    }

    // ---- last-CTA finalize (threadfence reduction pattern) ----
    __threadfence();
    __syncthreads();
    __shared__ unsigned int s_last;
    if (tid == 0)
        s_last = (atomicAdd(&g_done, 1u) == (unsigned)(NCTAS - 1)) ? 1u : 0u;
    __syncthreads();

    if (s_last) {
        __threadfence();   // acquire: see all CTAs' partial stores
        float* red = (float*)(smem + SM_RED);
        float acc2 = 0.0f;
#pragma unroll
        for (int rep = 0; rep < 4; rep++) {
            const int p = tid + rep * 512;
            float rs = 0.0f, cs = 0.0f;
#pragma unroll
            for (int s = 0; s < NBX; s++) rs += g_RowP[s][p];
#pragma unroll
            for (int s = 0; s < NBY; s++) cs += g_ColP[s][p];
            const float J = logf(1e-8f + rs + cs) - g_Dpos[p];
            const float t = fmaxf(J, 0.0f);
            acc2 += t * t;
        }
        red[tid] = acc2;
        __syncthreads();
        for (int off = 256; off > 0; off >>= 1) {
            if (tid < off) red[tid] += red[tid + off];
            __syncthreads();
        }
        if (tid == 0) {
            out[0] = red[0] * (1.0f / 4096.0f);
            g_done = 0;    // reset for next graph replay
        }
    }
}

// ---------------------------------------------------------------------------
extern "C" void kernel_launch(void* const* d_in, const int* in_sizes, int n_in,
                              void* d_out, int out_size) {
    const float* X = (const float*)d_in[0];
    float* out = (float*)d_out;

    cudaFuncSetAttribute(sml_fused, cudaFuncAttributeMaxDynamicSharedMemorySize,
                         SMEM_TOTAL);
    dim3 grid(NBX, NBY);   // 128 CTAs, single wave
    sml_fused<<<grid, 512, SMEM_TOTAL>>>(X, out);
}

// round 7
// speedup vs baseline: 1.2773x; 1.2773x over previous
#include <cuda_runtime.h>
#include <cuda_bf16.h>
#include <cstdint>
#include <math.h>

#define NP    2048
#define DFEAT 256
#define BT    128
#define NBLK  (NP / BT)        // 16
#define NCTAS (NBLK * NBLK)    // 256

// K streamed in 4 chunks of 64 bf16 (128B data + 16B pad per row)
#define ROWC   144
#define CHUNK_B (BT * ROWC)    // 18432
#define SM_A0  0
#define SM_A1  CHUNK_B
#define SM_B0  (2 * CHUNK_B)
#define SM_B1  (3 * CHUNK_B)
#define SM_RS  (4 * CHUNK_B)           // rsum[128]
#define SM_CS  (4 * CHUNK_B + 512)     // csum[128]
#define SM_RED (4 * CHUNK_B + 1024)    // red[256]
#define SMEM_TOTAL (4 * CHUNK_B + 2048)  // 75776 B -> 2 CTAs/SM

// -------- device scratch --------
__device__ __align__(16) __nv_bfloat16 g_Abf[NP * DFEAT];  // X[2p]
__device__ __align__(16) __nv_bfloat16 g_Bbf[NP * DFEAT];  // X[2p+1]
__device__ float g_RowP[NBLK][NP];
__device__ float g_ColP[NBLK][NP];
__device__ float g_Dpos[NP];
__device__ unsigned int g_done = 0;

static __device__ __forceinline__ uint32_t smem_u32(const void* p) {
    return (uint32_t)__cvta_generic_to_shared((void*)p);
}

static __device__ __forceinline__ void cpasync16(uint32_t dst, const void* src) {
    asm volatile("cp.async.cg.shared.global [%0], [%1], 16;"
                 :: "r"(dst), "l"(src));
}
#define CP_COMMIT() asm volatile("cp.async.commit_group;" ::: "memory")
#define CP_WAIT(N)  asm volatile("cp.async.wait_group %0;" :: "n"(N) : "memory")

static __device__ __forceinline__ void ldsm_x4(uint32_t* r, uint32_t addr) {
    asm volatile("ldmatrix.sync.aligned.m8n8.x4.shared.b16 {%0,%1,%2,%3}, [%4];"
                 : "=r"(r[0]), "=r"(r[1]), "=r"(r[2]), "=r"(r[3]) : "r"(addr));
}

static __device__ __forceinline__ void mma16816(float* c, const uint32_t* a,
                                                const uint32_t* b) {
    asm volatile(
        "mma.sync.aligned.m16n8k16.row.col.f32.bf16.bf16.f32 "
        "{%0,%1,%2,%3}, {%4,%5,%6,%7}, {%8,%9}, {%0,%1,%2,%3};"
        : "+f"(c[0]), "+f"(c[1]), "+f"(c[2]), "+f"(c[3])
        : "r"(a[0]), "r"(a[1]), "r"(a[2]), "r"(a[3]), "r"(b[0]), "r"(b[1]));
}

// ---------------------------------------------------------------------------
// Kernel 1: fp32 -> bf16 + even/odd deinterleave. 4 float4/thread (MLP 4).
// ---------------------------------------------------------------------------
__global__ void sml_convert(const float* __restrict__ X) {
    const int base = blockIdx.x * blockDim.x + threadIdx.x;
#pragma unroll
    for (int s = 0; s < 4; s++) {
        const int i = base + s * 65536;            // float4 index
        const float4 v = ((const float4*)X)[i];
        const int row = i >> 6;
        const int k4  = i & 63;
        const int p   = row >> 1;
        __nv_bfloat162 lo = __float22bfloat162_rn(make_float2(v.x, v.y));
        __nv_bfloat162 hi = __float22bfloat162_rn(make_float2(v.z, v.w));
        __nv_bfloat16* dst = (row & 1) ? g_Bbf : g_Abf;
        uint2 packed;
        packed.x = *(uint32_t*)&lo;
        packed.y = *(uint32_t*)&hi;
        *(uint2*)&dst[p * DFEAT + k4 * 4] = packed;
    }
}

// ---------------------------------------------------------------------------
// Kernel 2: 128x128 tile, cp.async double-buffered K-chunks of 64,
// 256 threads = 8 warps (4M x 2N), fused exp epilogue + last-CTA finalize.
// ---------------------------------------------------------------------------
__global__ __launch_bounds__(256, 2)
void sml_gemm(float* __restrict__ out) {
    extern __shared__ char smem[];
    const uint32_t sbase = smem_u32(smem);
    float* rsum = (float*)(smem + SM_RS);
    float* csum = (float*)(smem + SM_CS);

    const int tid = threadIdx.x;
    const int wid = tid >> 5;
    const int l   = tid & 31;
    const int wm  = wid & 3;
    const int wn  = wid >> 2;
    const int bx = blockIdx.x, by = blockIdx.y;
    const int r0 = by * BT, c0 = bx * BT;

    if (tid < 128) { rsum[tid] = 0.0f; csum[tid] = 0.0f; }

    // loader mapping: 4 iters -> idx = tid + 256*i; row = idx>>3, seg = idx&7
    const int ld_row = tid >> 3;         // base row (0..31), +32 per iter
    const int ld_seg = tid & 7;

    // issue one K-chunk (A and B) into the given buffers
    auto issue_chunk = [&](int c, uint32_t aoff, uint32_t boff) {
#pragma unroll
        for (int i = 0; i < 4; i++) {
            const int row = ld_row + 32 * i;
            cpasync16(sbase + aoff + row * ROWC + ld_seg * 16,
                      &g_Abf[(size_t)(r0 + row) * DFEAT + c * 64 + ld_seg * 8]);
        }
#pragma unroll
        for (int i = 0; i < 4; i++) {
            const int row = ld_row + 32 * i;
            cpasync16(sbase + boff + row * ROWC + ld_seg * 16,
                      &g_Bbf[(size_t)(c0 + row) * DFEAT + c * 64 + ld_seg * 8]);
        }
        CP_COMMIT();
    };

    // ldmatrix lane addressing (validated rounds 4-6), chunk-relative
    const int a_row = (l & 7) + 8 * ((l >> 3) & 1);
    const int a_kb  = 16 * ((l >> 4) & 1);
    const int b_row = (l & 7) + 8 * ((l >> 4) & 1);
    const int b_kb  = 16 * ((l >> 3) & 1);
    const uint32_t aRel = (uint32_t)(wm * 32 + a_row) * ROWC + a_kb;
    const uint32_t bRel = (uint32_t)(wn * 64 + b_row) * ROWC + b_kb;

    float acc[2][8][4];
#pragma unroll
    for (int mt = 0; mt < 2; mt++)
#pragma unroll
        for (int nt = 0; nt < 8; nt++)
#pragma unroll
            for (int r = 0; r < 4; r++) acc[mt][nt][r] = 0.0f;

    auto compute_chunk = [&](uint32_t aoff, uint32_t boff) {
        const uint32_t aAddr0 = sbase + aoff + aRel;
        const uint32_t bAddr0 = sbase + boff + bRel;
#pragma unroll
        for (int kk = 0; kk < 4; kk++) {
            const uint32_t koff = (uint32_t)kk * 32;
            uint32_t a[2][4];
            ldsm_x4(a[0], aAddr0 + koff);
            ldsm_x4(a[1], aAddr0 + 16 * ROWC + koff);
            uint32_t b[8][2];
#pragma unroll
            for (int q = 0; q < 4; q++) {
                uint32_t t[4];
                ldsm_x4(t, bAddr0 + (uint32_t)(q * 16) * ROWC + koff);
                b[2 * q][0] = t[0];      b[2 * q][1] = t[1];
                b[2 * q + 1][0] = t[2];  b[2 * q + 1][1] = t[3];
            }
#pragma unroll
            for (int mt = 0; mt < 2; mt++)
#pragma unroll
                for (int nt = 0; nt < 8; nt++)
                    mma16816(acc[mt][nt], a[mt], b[nt]);
        }
    };

    // ---- pipelined mainloop: chunks 0..3, double buffer ----
    issue_chunk(0, SM_A0, SM_B0);
    issue_chunk(1, SM_A1, SM_B1);

    CP_WAIT(1); __syncthreads();          // chunk 0 ready
    compute_chunk(SM_A0, SM_B0);
    __syncthreads();                      // all done reading buf0
    issue_chunk(2, SM_A0, SM_B0);

    CP_WAIT(1); __syncthreads();          // chunk 1 ready
    compute_chunk(SM_A1, SM_B1);
    __syncthreads();
    issue_chunk(3, SM_A1, SM_B1);

    CP_WAIT(1); __syncthreads();          // chunk 2 ready
    compute_chunk(SM_A0, SM_B0);

    CP_WAIT(0); __syncthreads();          // chunk 3 ready
    compute_chunk(SM_A1, SM_B1);

    // ---- epilogue: exp, masked row/col partials, Dpos ----
    float rowp[2][2];
    float colp[8][2];
#pragma unroll
    for (int mt = 0; mt < 2; mt++)
#pragma unroll
        for (int h = 0; h < 2; h++) rowp[mt][h] = 0.0f;
#pragma unroll
    for (int nt = 0; nt < 8; nt++)
#pragma unroll
        for (int j = 0; j < 2; j++) colp[nt][j] = 0.0f;

#pragma unroll
    for (int mt = 0; mt < 2; mt++) {
#pragma unroll
        for (int h = 0; h < 2; h++) {
            const int gr = r0 + wm * 32 + mt * 16 + h * 8 + (l >> 2);
            const int rexcl = 2 * gr + 1;
#pragma unroll
            for (int nt = 0; nt < 8; nt++) {
#pragma unroll
                for (int j = 0; j < 2; j++) {
                    const int gc = c0 + wn * 64 + nt * 8 + 2 * (l & 3) + j;
                    const float e = acc[mt][nt][2 * h + j] * (1.0f / 128.0f);
                    const float x = __expf(1.0f + e);
                    if (gc != rexcl)  rowp[mt][h] += x;
                    if (gr != 2 * gc) colp[nt][j] += x;
                    if (gr == gc)     g_Dpos[gr] = e;
                }
            }
        }
    }

#pragma unroll
    for (int mt = 0; mt < 2; mt++) {
#pragma unroll
        for (int h = 0; h < 2; h++) {
            float v = rowp[mt][h];
            v += __shfl_xor_sync(0xFFFFFFFFu, v, 1);
            v += __shfl_xor_sync(0xFFFFFFFFu, v, 2);
            if ((l & 3) == 0)
                atomicAdd(&rsum[wm * 32 + mt * 16 + h * 8 + (l >> 2)], v);
        }
    }
#pragma unroll
    for (int nt = 0; nt < 8; nt++) {
#pragma unroll
        for (int j = 0; j < 2; j++) {
            float v = colp[nt][j];
            v += __shfl_xor_sync(0xFFFFFFFFu, v, 4);
            v += __shfl_xor_sync(0xFFFFFFFFu, v, 8);
            v += __shfl_xor_sync(0xFFFFFFFFu, v, 16);
            if ((l >> 2) == 0)
                atomicAdd(&csum[wn * 64 + nt * 8 + 2 * (l & 3) + j], v);
        }
    }
    __syncthreads();

    if (tid < 128) {
        g_RowP[bx][r0 + tid] = rsum[tid];
    } else {
        g_ColP[by][c0 + tid - 128] = csum[tid - 128];
    }

    // ---- last-CTA finalize (validated round 6) ----
    __threadfence();
    __syncthreads();
    __shared__ unsigned int s_last;
    if (tid == 0)
        s_last = (atomicAdd(&g_done, 1u) == (unsigned)(NCTAS - 1)) ? 1u : 0u;
    __syncthreads();

    if (s_last) {
        __threadfence();
        float* red = (float*)(smem + SM_RED);
        float acc2 = 0.0f;
#pragma unroll
        for (int rep = 0; rep < 8; rep++) {
            const int p = tid + rep * 256;
            float rs = 0.0f, cs = 0.0f;
#pragma unroll
            for (int s = 0; s < NBLK; s++) {
                rs += g_RowP[s][p];
                cs += g_ColP[s][p];
            }
            const float J = logf(1e-8f + rs + cs) - g_Dpos[p];
            const float t = fmaxf(J, 0.0f);
            acc2 += t * t;
        }
        red[tid] = acc2;
        __syncthreads();
        for (int off = 128; off > 0; off >>= 1) {
            if (tid < off) red[tid] += red[tid + off];
            __syncthreads();
        }
        if (tid == 0) {
            out[0] = red[0] * (1.0f / 4096.0f);
            g_done = 0;
        }
    }
}

// ---------------------------------------------------------------------------
extern "C" void kernel_launch(void* const* d_in, const int* in_sizes, int n_in,
                              void* d_out, int out_size) {
    const float* X = (const float*)d_in[0];
    float* out = (float*)d_out;

    sml_convert<<<256, 256>>>(X);

    cudaFuncSetAttribute(sml_gemm, cudaFuncAttributeMaxDynamicSharedMemorySize,
                         SMEM_TOTAL);
    dim3 grid(NBLK, NBLK);   // 16 x 16 = 256 CTAs, 2/SM
    sml_gemm<<<grid, 256, SMEM_TOTAL>>>(out);
}